// round 6
// baseline (speedup 1.0000x reference)
#include <cuda_runtime.h>
#include <math.h>
#include <stdint.h>

// Problem constants
#define BSZ    8
#define LSEQ   1024
#define DMODEL 1024
#define NSTATE 16
#define MTOT   (BSZ * LSEQ)        // 8192
#define XTOT   (MTOT * DMODEL)     // 8388608
#define KDIM   1024

// GEMM tiling
#define BM 128
#define BN 128
#define BK 32
#define NSTG 2
#define NCHUNK (KDIM / BK)          // 32
#define SSTRIDE 520                 // words per kk4 slab (128*4 + 8 pad)
#define ASTAGE_W (8 * SSTRIDE)      // 4160 words per operand per stage
#define STAGE_W  (2 * ASTAGE_W)     // 8320 words
#define SMEM_DYN (NSTG * STAGE_W * 4)   // 66560 bytes

// N sizes
#define N1 2048
#define N2 1152                     // 1024 dt + 16 B + 16 C + 96 pad
#define N3 1024

// ---------------------------------------------------------------------------
// Scratch
// ---------------------------------------------------------------------------
__device__ __align__(256) float g_xnorm[XTOT];          // tf32-rounded
__device__ __align__(256) float g_xin[XTOT];            // fp32 (scan)
__device__ __align__(256) float g_xin_r[XTOT];          // tf32-rounded (gemm A)
__device__ __align__(256) float g_z[XTOT];
__device__ __align__(256) float g_dt[XTOT];
__device__ __align__(256) float g_Bt[MTOT * NSTATE];
__device__ __align__(256) float g_Ct[MTOT * NSTATE];
__device__ __align__(256) float g_ssm[XTOT];            // tf32-rounded
__device__ __align__(256) float g_wigr[N1 * KDIM];      // rounded W_ig
__device__ __align__(256) float g_wbc[N2 * KDIM];       // rounded [W_dt;W_B;W_C;0]
__device__ __align__(256) float g_woutr[N3 * KDIM];     // rounded W_out

// ---------------------------------------------------------------------------
// Helpers
// ---------------------------------------------------------------------------
__device__ __forceinline__ uint32_t f2tf(float f) {
    uint32_t u;
    asm("cvt.rna.tf32.f32 %0, %1;" : "=r"(u) : "f"(f));
    return u;
}
__device__ __forceinline__ float f2tf_f(float f) { return __uint_as_float(f2tf(f)); }

__device__ __forceinline__ void mma_tf32(float* c, const uint32_t* a, const uint32_t* b) {
    asm volatile(
        "mma.sync.aligned.m16n8k8.row.col.f32.tf32.tf32.f32 "
        "{%0,%1,%2,%3}, {%4,%5,%6,%7}, {%8,%9}, {%0,%1,%2,%3};"
        : "+f"(c[0]), "+f"(c[1]), "+f"(c[2]), "+f"(c[3])
        : "r"(a[0]), "r"(a[1]), "r"(a[2]), "r"(a[3]), "r"(b[0]), "r"(b[1]));
}

__device__ __forceinline__ uint32_t smem_u32(const void* p) {
    uint32_t a;
    asm("{ .reg .u64 t; cvta.to.shared.u64 t, %1; cvt.u32.u64 %0, t; }" : "=r"(a) : "l"(p));
    return a;
}
__device__ __forceinline__ void cp16(uint32_t dst, const float* src) {
    asm volatile("cp.async.cg.shared.global [%0], [%1], 16;"
                 :: "r"(dst), "l"(__cvta_generic_to_global(src)));
}
#define CP_COMMIT() asm volatile("cp.async.commit_group;")
#define CP_WAIT0()  asm volatile("cp.async.wait_group 0;" ::: "memory")

__device__ __forceinline__ float softplus_f(float v) {
    return (v > 20.f) ? v : log1pf(expf(v));
}

// ---------------------------------------------------------------------------
// LayerNorm (tf32-rounded output; sole consumer is gemm1's A operand)
// ---------------------------------------------------------------------------
__global__ __launch_bounds__(256) void layernorm_kernel(
    const float* __restrict__ x,
    const float* __restrict__ g,
    const float* __restrict__ b)
{
    int row = blockIdx.x;
    int t = threadIdx.x;
    float4 v = reinterpret_cast<const float4*>(x + (size_t)row * DMODEL)[t];

    float s  = v.x + v.y + v.z + v.w;
    float sq = v.x * v.x + v.y * v.y + v.z * v.z + v.w * v.w;
    #pragma unroll
    for (int o = 16; o; o >>= 1) {
        s  += __shfl_xor_sync(0xffffffffu, s,  o);
        sq += __shfl_xor_sync(0xffffffffu, sq, o);
    }
    __shared__ float ssum[8], ssq[8], sh_mean, sh_rstd;
    int w = t >> 5;
    if ((t & 31) == 0) { ssum[w] = s; ssq[w] = sq; }
    __syncthreads();
    if (t == 0) {
        float S = 0.f, Q = 0.f;
        #pragma unroll
        for (int i = 0; i < 8; i++) { S += ssum[i]; Q += ssq[i]; }
        float mu  = S * (1.0f / DMODEL);
        float var = Q * (1.0f / DMODEL) - mu * mu;
        sh_mean = mu;
        sh_rstd = rsqrtf(var + 1e-5f);
    }
    __syncthreads();
    float mean = sh_mean, rstd = sh_rstd;

    float4 gg = reinterpret_cast<const float4*>(g)[t];
    float4 bb = reinterpret_cast<const float4*>(b)[t];
    float4 o;
    o.x = f2tf_f((v.x - mean) * rstd * gg.x + bb.x);
    o.y = f2tf_f((v.y - mean) * rstd * gg.y + bb.y);
    o.z = f2tf_f((v.z - mean) * rstd * gg.z + bb.z);
    o.w = f2tf_f((v.w - mean) * rstd * gg.w + bb.w);
    reinterpret_cast<float4*>(g_xnorm + (size_t)row * DMODEL)[t] = o;
}

// ---------------------------------------------------------------------------
// Weight prep: tf32-round all B operands; assemble fused [W_dt; W_B; W_C; 0]
// (rows 1056..1151 of g_wbc stay zero from static init)
// ---------------------------------------------------------------------------
__global__ __launch_bounds__(256) void prep_kernel(
    const float* __restrict__ W_ig,
    const float* __restrict__ W_dt,
    const float* __restrict__ W_B,
    const float* __restrict__ W_C,
    const float* __restrict__ W_out)
{
    const int K4 = KDIM / 4;
    int stride = gridDim.x * blockDim.x;
    const int nig  = N1 * K4;
    const int nbc  = 1056 * K4;
    const int nout = N3 * K4;
    int total = nig + nbc + nout;
    for (int i = blockIdx.x * blockDim.x + threadIdx.x; i < total; i += stride) {
        const float4* src;
        float4* dst;
        if (i < nig) {
            src = reinterpret_cast<const float4*>(W_ig) + i;
            dst = reinterpret_cast<float4*>(g_wigr) + i;
        } else if (i < nig + nbc) {
            int j = i - nig;
            int row = j / K4;
            int c4  = j % K4;
            const float* s;
            if (row < 1024)      s = W_dt + (size_t)row * KDIM;
            else if (row < 1040) s = W_B + (size_t)(row - 1024) * KDIM;
            else                 s = W_C + (size_t)(row - 1040) * KDIM;
            src = reinterpret_cast<const float4*>(s) + c4;
            dst = reinterpret_cast<float4*>(g_wbc) + j;
        } else {
            int j = i - nig - nbc;
            src = reinterpret_cast<const float4*>(W_out) + j;
            dst = reinterpret_cast<float4*>(g_woutr) + j;
        }
        float4 v = *src;
        v.x = f2tf_f(v.x); v.y = f2tf_f(v.y); v.z = f2tf_f(v.z); v.w = f2tf_f(v.w);
        *dst = v;
    }
}

// ---------------------------------------------------------------------------
// TF32 mma.sync GEMM, cp.async 2-stage pipeline, 3 CTAs/SM target.
// C[m,n] = sum_k A[m,k]*B[n,k]; tile 128x128, 8 warps (2m x 4n), warp 64x32.
// EPI 1: n<1024 -> O0 (fp32 x_in) + O2 (tf32 copy); else O1 (z)
// EPI 2: n<1024 -> softplus(v+aux[n]) -> O0; 1024-1039 -> O1(Bt);
//        1040-1055 -> O2(Ct); else discard
// EPI 3: O0 = v + aux[m*1024+n]
// ---------------------------------------------------------------------------
template<int EPI>
__global__ __launch_bounds__(256, 3) void gemm_ma(
    const float* __restrict__ A,
    const float* __restrict__ Bw,
    float* __restrict__ O0,
    float* __restrict__ O1,
    float* __restrict__ O2,
    const float* __restrict__ aux)
{
    extern __shared__ uint32_t dsm[];
    const uint32_t dsm_addr = smem_u32(dsm);

    const int tid  = threadIdx.x;
    const int wid  = tid >> 5;
    const int lane = tid & 31;
    const int bm   = blockIdx.y * BM;
    const int bn   = blockIdx.x * BN;
    const int wm   = wid >> 2;
    const int wn   = wid & 3;
    const int g    = lane >> 2;
    const int t4   = lane & 3;

    const float* Ag = A  + (size_t)bm * KDIM;
    const float* Bg = Bw + (size_t)bn * KDIM;

    const int lrow = tid >> 3;      // 0..31 (+k*32)
    const int lc4  = tid & 7;

    auto load_chunk = [&](int c, int stg) {
        uint32_t base = dsm_addr + (uint32_t)(stg * STAGE_W * 4);
        uint32_t wdst = (uint32_t)((lc4 * SSTRIDE) * 4);
        #pragma unroll
        for (int it = 0; it < 4; it++) {
            int row = lrow + it * 32;
            cp16(base + wdst + (uint32_t)(row * 16),
                 Ag + (size_t)row * KDIM + c * BK + lc4 * 4);
        }
        uint32_t baseB = base + (uint32_t)(ASTAGE_W * 4);
        #pragma unroll
        for (int it = 0; it < 4; it++) {
            int row = lrow + it * 32;
            cp16(baseB + wdst + (uint32_t)(row * 16),
                 Bg + (size_t)row * KDIM + c * BK + lc4 * 4);
        }
    };

    float acc[4][4][4];
    #pragma unroll
    for (int i = 0; i < 4; i++)
        #pragma unroll
        for (int j = 0; j < 4; j++)
            #pragma unroll
            for (int r = 0; r < 4; r++) acc[i][j][r] = 0.f;

    // prologue: chunk 0
    load_chunk(0, 0); CP_COMMIT();

    for (int c = 0; c < NCHUNK; c++) {
        CP_WAIT0();
        __syncthreads();    // all loads of chunk c landed; all reads of the
                            // stage about to be overwritten are done

        if (c + 1 < NCHUNK) { load_chunk(c + 1, (c + 1) & 1); CP_COMMIT(); }

        const uint32_t* sA = dsm + (c & 1) * STAGE_W;
        const uint32_t* sAm = sA + (wm * 64) * 4 + t4;
        const uint32_t* sBn = sA + ASTAGE_W + (wn * 32) * 4 + t4;

        #pragma unroll
        for (int s = 0; s < 4; s++) {
            const int lo = (2 * s) * SSTRIDE;
            const int hi = lo + SSTRIDE;
            uint32_t bf[4][2];
            #pragma unroll
            for (int nt = 0; nt < 4; nt++) {
                int no = (nt * 8 + g) * 4;
                bf[nt][0] = sBn[lo + no];
                bf[nt][1] = sBn[hi + no];
            }
            #pragma unroll
            for (int mt = 0; mt < 4; mt++) {
                uint32_t af[4];
                int mo = (mt * 16 + g) * 4;
                af[0] = sAm[lo + mo];
                af[1] = sAm[lo + mo + 32];
                af[2] = sAm[hi + mo];
                af[3] = sAm[hi + mo + 32];
                #pragma unroll
                for (int nt = 0; nt < 4; nt++)
                    mma_tf32(acc[mt][nt], af, bf[nt]);
            }
        }
        // no trailing barrier: next chunk's top barrier protects stage reuse
    }

    // Epilogue
    #pragma unroll
    for (int mt = 0; mt < 4; mt++) {
        #pragma unroll
        for (int nt = 0; nt < 4; nt++) {
            int m0 = bm + wm * 64 + mt * 16 + g;
            int n0 = bn + wn * 32 + nt * 8 + 2 * t4;
            float* cc = acc[mt][nt];
            #pragma unroll
            for (int half = 0; half < 2; half++) {
                int m = m0 + half * 8;
                float v0 = cc[half * 2 + 0];
                float v1 = cc[half * 2 + 1];
                if constexpr (EPI == 1) {
                    if (n0 < DMODEL) {
                        *reinterpret_cast<float2*>(&O0[(size_t)m * DMODEL + n0]) = make_float2(v0, v1);
                        *reinterpret_cast<float2*>(&O2[(size_t)m * DMODEL + n0]) =
                            make_float2(f2tf_f(v0), f2tf_f(v1));
                    } else {
                        *reinterpret_cast<float2*>(&O1[(size_t)m * DMODEL + n0 - DMODEL]) = make_float2(v0, v1);
                    }
                } else if constexpr (EPI == 2) {
                    if (n0 < DMODEL) {
                        v0 = softplus_f(v0 + aux[n0]);
                        v1 = softplus_f(v1 + aux[n0 + 1]);
                        *reinterpret_cast<float2*>(&O0[(size_t)m * DMODEL + n0]) = make_float2(v0, v1);
                    } else if (n0 < 1040) {
                        *reinterpret_cast<float2*>(&O1[(size_t)m * NSTATE + (n0 - 1024)]) = make_float2(v0, v1);
                    } else if (n0 < 1056) {
                        *reinterpret_cast<float2*>(&O2[(size_t)m * NSTATE + (n0 - 1040)]) = make_float2(v0, v1);
                    }
                } else { // EPI == 3
                    float2 r = *reinterpret_cast<const float2*>(&aux[(size_t)m * DMODEL + n0]);
                    *reinterpret_cast<float2*>(&O0[(size_t)m * DMODEL + n0]) = make_float2(v0 + r.x, v1 + r.y);
                }
            }
        }
    }
}

// ---------------------------------------------------------------------------
// Sequential SSM scan + fused silu/D epilogue, 1-step-ahead prefetch.
// ---------------------------------------------------------------------------
__global__ __launch_bounds__(256) void scan_kernel(
    const float* __restrict__ A_log,
    const float* __restrict__ h_prev,
    const float* __restrict__ Dvec,
    float* __restrict__ h_out)
{
    int b  = blockIdx.x >> 6;
    int dg = blockIdx.x & 63;
    int n  = threadIdx.x & 15;
    int dl = threadIdx.x >> 4;
    int d  = dg * 16 + dl;

    float Acoef = -__expf(A_log[d * NSTATE + n]);
    float h  = h_prev[((size_t)b * DMODEL + d) * NSTATE + n];
    float Dd = Dvec[d];
    const bool lead = (n == 0);

    size_t idx  = (size_t)b * LSEQ * DMODEL + d;
    size_t idxn = (size_t)b * LSEQ * NSTATE + n;

    float dtv = g_dt[idx];
    float xin = g_xin[idx];
    float Btv = g_Bt[idxn];
    float Ctv = g_Ct[idxn];
    float zv  = lead ? g_z[idx] : 0.f;

    for (int t = 0; t < LSEQ; t++) {
        float n_dt = 0.f, n_xin = 0.f, n_Bt = 0.f, n_Ct = 0.f, n_z = 0.f;
        if (t + 1 < LSEQ) {
            n_dt  = g_dt[idx + DMODEL];
            n_xin = g_xin[idx + DMODEL];
            n_Bt  = g_Bt[idxn + NSTATE];
            n_Ct  = g_Ct[idxn + NSTATE];
            if (lead) n_z = g_z[idx + DMODEL];
        }

        float dA = __expf(dtv * Acoef);
        h = dA * h + (dtv * xin) * Btv;
        float y = h * Ctv;
        y += __shfl_xor_sync(0xffffffffu, y, 1);
        y += __shfl_xor_sync(0xffffffffu, y, 2);
        y += __shfl_xor_sync(0xffffffffu, y, 4);
        y += __shfl_xor_sync(0xffffffffu, y, 8);

        if (lead) {
            float sil = zv / (1.f + __expf(-zv));
            g_ssm[idx] = f2tf_f(y * sil + xin * Dd);
        }

        dtv = n_dt; xin = n_xin; Btv = n_Bt; Ctv = n_Ct; zv = n_z;
        idx += DMODEL; idxn += NSTATE;
    }
    h_out[((size_t)b * DMODEL + d) * NSTATE + n] = h;
}

// ---------------------------------------------------------------------------
// Launch
// ---------------------------------------------------------------------------
extern "C" void kernel_launch(void* const* d_in, const int* in_sizes, int n_in,
                              void* d_out, int out_size)
{
    const float* x      = (const float*)d_in[0];
    const float* h_prev = (const float*)d_in[1];
    const float* ln_g   = (const float*)d_in[2];
    const float* ln_b   = (const float*)d_in[3];
    const float* W_ig   = (const float*)d_in[4];
    const float* W_dt   = (const float*)d_in[5];
    const float* b_dt   = (const float*)d_in[6];
    const float* A_log  = (const float*)d_in[7];
    const float* W_B    = (const float*)d_in[8];
    const float* W_C    = (const float*)d_in[9];
    const float* Dv     = (const float*)d_in[10];
    const float* W_out  = (const float*)d_in[11];
    float* out = (float*)d_out;

    float *p_xnorm, *p_xin, *p_xin_r, *p_z, *p_dt, *p_Bt, *p_Ct, *p_ssm;
    float *p_wigr, *p_wbc, *p_woutr;
    cudaGetSymbolAddress((void**)&p_xnorm, g_xnorm);
    cudaGetSymbolAddress((void**)&p_xin,   g_xin);
    cudaGetSymbolAddress((void**)&p_xin_r, g_xin_r);
    cudaGetSymbolAddress((void**)&p_z,     g_z);
    cudaGetSymbolAddress((void**)&p_dt,    g_dt);
    cudaGetSymbolAddress((void**)&p_Bt,    g_Bt);
    cudaGetSymbolAddress((void**)&p_Ct,    g_Ct);
    cudaGetSymbolAddress((void**)&p_ssm,   g_ssm);
    cudaGetSymbolAddress((void**)&p_wigr,  g_wigr);
    cudaGetSymbolAddress((void**)&p_wbc,   g_wbc);
    cudaGetSymbolAddress((void**)&p_woutr, g_woutr);

    cudaFuncSetAttribute(gemm_ma<1>, cudaFuncAttributeMaxDynamicSharedMemorySize, SMEM_DYN);
    cudaFuncSetAttribute(gemm_ma<2>, cudaFuncAttributeMaxDynamicSharedMemorySize, SMEM_DYN);
    cudaFuncSetAttribute(gemm_ma<3>, cudaFuncAttributeMaxDynamicSharedMemorySize, SMEM_DYN);

    // 0. weight prep (tf32 rounding + fused W' assembly)
    prep_kernel<<<2048, 256>>>(W_ig, W_dt, W_B, W_C, W_out);

    // 1. LayerNorm (tf32-rounded output)
    layernorm_kernel<<<MTOT, 256>>>(x, ln_g, ln_b);

    // 2. x_proj = x_norm @ W_ig^T -> x_in (fp32 + tf32 copy) | z
    {
        dim3 grid(N1 / BN, MTOT / BM);
        gemm_ma<1><<<grid, 256, SMEM_DYN>>>(p_xnorm, p_wigr, p_xin, p_z, p_xin_r, nullptr);
    }

    // 3. fused: dt = softplus(x_in@W_dt^T + b_dt); Bt; Ct
    {
        dim3 grid(N2 / BN, MTOT / BM);
        gemm_ma<2><<<grid, 256, SMEM_DYN>>>(p_xin_r, p_wbc, p_dt, p_Bt, p_Ct, b_dt);
    }

    // 4. scan -> g_ssm (tf32-rounded), h_final -> out tail
    scan_kernel<<<BSZ * 64, 256>>>(A_log, h_prev, Dv, out + XTOT);

    // 5. out = x + ssm @ W_out^T
    {
        dim3 grid(N3 / BN, MTOT / BM);
        gemm_ma<3><<<grid, 256, SMEM_DYN>>>(p_ssm, p_woutr, out, nullptr, nullptr, x);
    }
}

// round 7
// speedup vs baseline: 1.0908x; 1.0908x over previous
#include <cuda_runtime.h>
#include <math.h>
#include <stdint.h>

// Problem constants
#define BSZ    8
#define LSEQ   1024
#define DMODEL 1024
#define NSTATE 16
#define MTOT   (BSZ * LSEQ)        // 8192
#define XTOT   (MTOT * DMODEL)     // 8388608
#define KDIM   1024

// GEMM tiling
#define BM 128
#define BN 128
#define BK 16
#define NSTG 4
#define NCHUNK (KDIM / BK)          // 64
#define SSTRIDE 520                 // words per kk4 slab (128*4 + 8 pad)
#define ASTAGE_W (4 * SSTRIDE)      // 2080 words per operand per stage (4 slabs)
#define STAGE_W  (2 * ASTAGE_W)     // 4160 words
#define SMEM_DYN (NSTG * STAGE_W * 4)   // 66560 bytes

// N sizes
#define N1 2048
#define N2 1152                     // 1024 dt + 16 B + 16 C + 96 pad
#define N3 1024

// ---------------------------------------------------------------------------
// Scratch
// ---------------------------------------------------------------------------
__device__ __align__(256) float g_xnorm[XTOT];          // tf32-rounded
__device__ __align__(256) float g_xin[XTOT];            // fp32 (scan)
__device__ __align__(256) float g_xin_r[XTOT];          // tf32-rounded (gemm A)
__device__ __align__(256) float g_z[XTOT];
__device__ __align__(256) float g_dt[XTOT];
__device__ __align__(256) float g_Bt[MTOT * NSTATE];
__device__ __align__(256) float g_Ct[MTOT * NSTATE];
__device__ __align__(256) float g_ssm[XTOT];            // tf32-rounded
__device__ __align__(256) float g_wigr[N1 * KDIM];      // rounded W_ig
__device__ __align__(256) float g_wbc[N2 * KDIM];       // rounded [W_dt;W_B;W_C;0]
__device__ __align__(256) float g_woutr[N3 * KDIM];     // rounded W_out

// ---------------------------------------------------------------------------
// Helpers
// ---------------------------------------------------------------------------
__device__ __forceinline__ uint32_t f2tf(float f) {
    uint32_t u;
    asm("cvt.rna.tf32.f32 %0, %1;" : "=r"(u) : "f"(f));
    return u;
}
__device__ __forceinline__ float f2tf_f(float f) { return __uint_as_float(f2tf(f)); }

__device__ __forceinline__ void mma_tf32(float* c, const uint32_t* a, const uint32_t* b) {
    asm volatile(
        "mma.sync.aligned.m16n8k8.row.col.f32.tf32.tf32.f32 "
        "{%0,%1,%2,%3}, {%4,%5,%6,%7}, {%8,%9}, {%0,%1,%2,%3};"
        : "+f"(c[0]), "+f"(c[1]), "+f"(c[2]), "+f"(c[3])
        : "r"(a[0]), "r"(a[1]), "r"(a[2]), "r"(a[3]), "r"(b[0]), "r"(b[1]));
}

__device__ __forceinline__ uint32_t smem_u32(const void* p) {
    uint32_t a;
    asm("{ .reg .u64 t; cvta.to.shared.u64 t, %1; cvt.u32.u64 %0, t; }" : "=r"(a) : "l"(p));
    return a;
}
__device__ __forceinline__ void cp16(uint32_t dst, const float* src) {
    asm volatile("cp.async.cg.shared.global [%0], [%1], 16;"
                 :: "r"(dst), "l"(__cvta_generic_to_global(src)));
}
#define CP_COMMIT() asm volatile("cp.async.commit_group;")
#define CP_WAIT2()  asm volatile("cp.async.wait_group 2;" ::: "memory")

__device__ __forceinline__ float softplus_f(float v) {
    return (v > 20.f) ? v : log1pf(expf(v));
}

// ---------------------------------------------------------------------------
// LayerNorm (tf32-rounded output; sole consumer is gemm1's A operand)
// ---------------------------------------------------------------------------
__global__ __launch_bounds__(256) void layernorm_kernel(
    const float* __restrict__ x,
    const float* __restrict__ g,
    const float* __restrict__ b)
{
    int row = blockIdx.x;
    int t = threadIdx.x;
    float4 v = reinterpret_cast<const float4*>(x + (size_t)row * DMODEL)[t];

    float s  = v.x + v.y + v.z + v.w;
    float sq = v.x * v.x + v.y * v.y + v.z * v.z + v.w * v.w;
    #pragma unroll
    for (int o = 16; o; o >>= 1) {
        s  += __shfl_xor_sync(0xffffffffu, s,  o);
        sq += __shfl_xor_sync(0xffffffffu, sq, o);
    }
    __shared__ float ssum[8], ssq[8], sh_mean, sh_rstd;
    int w = t >> 5;
    if ((t & 31) == 0) { ssum[w] = s; ssq[w] = sq; }
    __syncthreads();
    if (t == 0) {
        float S = 0.f, Q = 0.f;
        #pragma unroll
        for (int i = 0; i < 8; i++) { S += ssum[i]; Q += ssq[i]; }
        float mu  = S * (1.0f / DMODEL);
        float var = Q * (1.0f / DMODEL) - mu * mu;
        sh_mean = mu;
        sh_rstd = rsqrtf(var + 1e-5f);
    }
    __syncthreads();
    float mean = sh_mean, rstd = sh_rstd;

    float4 gg = reinterpret_cast<const float4*>(g)[t];
    float4 bb = reinterpret_cast<const float4*>(b)[t];
    float4 o;
    o.x = f2tf_f((v.x - mean) * rstd * gg.x + bb.x);
    o.y = f2tf_f((v.y - mean) * rstd * gg.y + bb.y);
    o.z = f2tf_f((v.z - mean) * rstd * gg.z + bb.z);
    o.w = f2tf_f((v.w - mean) * rstd * gg.w + bb.w);
    reinterpret_cast<float4*>(g_xnorm + (size_t)row * DMODEL)[t] = o;
}

// ---------------------------------------------------------------------------
// Weight prep: tf32-round all B operands; assemble fused [W_dt; W_B; W_C; 0]
// (rows 1056..1151 of g_wbc stay zero from static init)
// ---------------------------------------------------------------------------
__global__ __launch_bounds__(256) void prep_kernel(
    const float* __restrict__ W_ig,
    const float* __restrict__ W_dt,
    const float* __restrict__ W_B,
    const float* __restrict__ W_C,
    const float* __restrict__ W_out)
{
    const int K4 = KDIM / 4;
    int stride = gridDim.x * blockDim.x;
    const int nig  = N1 * K4;
    const int nbc  = 1056 * K4;
    const int nout = N3 * K4;
    int total = nig + nbc + nout;
    for (int i = blockIdx.x * blockDim.x + threadIdx.x; i < total; i += stride) {
        const float4* src;
        float4* dst;
        if (i < nig) {
            src = reinterpret_cast<const float4*>(W_ig) + i;
            dst = reinterpret_cast<float4*>(g_wigr) + i;
        } else if (i < nig + nbc) {
            int j = i - nig;
            int row = j / K4;
            int c4  = j % K4;
            const float* s;
            if (row < 1024)      s = W_dt + (size_t)row * KDIM;
            else if (row < 1040) s = W_B + (size_t)(row - 1024) * KDIM;
            else                 s = W_C + (size_t)(row - 1040) * KDIM;
            src = reinterpret_cast<const float4*>(s) + c4;
            dst = reinterpret_cast<float4*>(g_wbc) + j;
        } else {
            int j = i - nig - nbc;
            src = reinterpret_cast<const float4*>(W_out) + j;
            dst = reinterpret_cast<float4*>(g_woutr) + j;
        }
        float4 v = *src;
        v.x = f2tf_f(v.x); v.y = f2tf_f(v.y); v.z = f2tf_f(v.z); v.w = f2tf_f(v.w);
        *dst = v;
    }
}

// ---------------------------------------------------------------------------
// TF32 mma.sync GEMM: BK=16, 4-stage cp.async pipeline (2-chunk prefetch
// depth), 3 CTAs/SM. Tile 128x128, 8 warps (2m x 4n), warp 64x32.
// EPI 1: n<1024 -> O0 (fp32 x_in) + O2 (tf32 copy); else O1 (z)
// EPI 2: n<1024 -> softplus(v+aux[n]) -> O0; 1024-1039 -> O1(Bt);
//        1040-1055 -> O2(Ct); else discard
// EPI 3: O0 = v + aux[m*1024+n]
// ---------------------------------------------------------------------------
template<int EPI>
__global__ __launch_bounds__(256, 3) void gemm_ma(
    const float* __restrict__ A,
    const float* __restrict__ Bw,
    float* __restrict__ O0,
    float* __restrict__ O1,
    float* __restrict__ O2,
    const float* __restrict__ aux)
{
    extern __shared__ uint32_t dsm[];
    const uint32_t dsm_addr = smem_u32(dsm);

    const int tid  = threadIdx.x;
    const int wid  = tid >> 5;
    const int lane = tid & 31;
    const int bm   = blockIdx.y * BM;
    const int bn   = blockIdx.x * BN;
    const int wm   = wid >> 2;
    const int wn   = wid & 3;
    const int g    = lane >> 2;
    const int t4   = lane & 3;

    const float* Ag = A  + (size_t)bm * KDIM;
    const float* Bg = Bw + (size_t)bn * KDIM;

    const int lrow = tid >> 2;      // 0..63 (+it*64)
    const int lkq  = tid & 3;       // k4 slab 0..3

    auto load_chunk = [&](int c, int stg) {
        uint32_t base = dsm_addr + (uint32_t)(stg * STAGE_W * 4);
        uint32_t wdst = (uint32_t)(lkq * SSTRIDE * 4);
        #pragma unroll
        for (int it = 0; it < 2; it++) {
            int row = lrow + it * 64;
            cp16(base + wdst + (uint32_t)(row * 16),
                 Ag + (size_t)row * KDIM + c * BK + lkq * 4);
        }
        uint32_t baseB = base + (uint32_t)(ASTAGE_W * 4);
        #pragma unroll
        for (int it = 0; it < 2; it++) {
            int row = lrow + it * 64;
            cp16(baseB + wdst + (uint32_t)(row * 16),
                 Bg + (size_t)row * KDIM + c * BK + lkq * 4);
        }
    };

    float acc[4][4][4];
    #pragma unroll
    for (int i = 0; i < 4; i++)
        #pragma unroll
        for (int j = 0; j < 4; j++)
            #pragma unroll
            for (int r = 0; r < 4; r++) acc[i][j][r] = 0.f;

    // prologue: chunks 0,1,2
    load_chunk(0, 0); CP_COMMIT();
    load_chunk(1, 1); CP_COMMIT();
    load_chunk(2, 2); CP_COMMIT();

    for (int c = 0; c < NCHUNK; c++) {
        CP_WAIT2();           // chunk c's group complete (2 younger in flight)
        __syncthreads();      // also: every warp done computing chunk c-1,
                              // so stage (c+3)%4 == (c-1)%4 is reusable

        if (c + 3 < NCHUNK) { load_chunk(c + 3, (c + 3) & (NSTG - 1)); CP_COMMIT(); }

        const uint32_t* sA = dsm + (c & (NSTG - 1)) * STAGE_W;
        const uint32_t* sAm = sA + (wm * 64) * 4 + t4;
        const uint32_t* sBn = sA + ASTAGE_W + (wn * 32) * 4 + t4;

        #pragma unroll
        for (int s = 0; s < 2; s++) {
            const int lo = (2 * s) * SSTRIDE;
            const int hi = lo + SSTRIDE;
            uint32_t bf[4][2];
            #pragma unroll
            for (int nt = 0; nt < 4; nt++) {
                int no = (nt * 8 + g) * 4;
                bf[nt][0] = sBn[lo + no];
                bf[nt][1] = sBn[hi + no];
            }
            #pragma unroll
            for (int mt = 0; mt < 4; mt++) {
                uint32_t af[4];
                int mo = (mt * 16 + g) * 4;
                af[0] = sAm[lo + mo];
                af[1] = sAm[lo + mo + 32];
                af[2] = sAm[hi + mo];
                af[3] = sAm[hi + mo + 32];
                #pragma unroll
                for (int nt = 0; nt < 4; nt++)
                    mma_tf32(acc[mt][nt], af, bf[nt]);
            }
        }
        // no trailing barrier: next chunk's top barrier protects stage reuse
    }

    // Epilogue
    #pragma unroll
    for (int mt = 0; mt < 4; mt++) {
        #pragma unroll
        for (int nt = 0; nt < 4; nt++) {
            int m0 = bm + wm * 64 + mt * 16 + g;
            int n0 = bn + wn * 32 + nt * 8 + 2 * t4;
            float* cc = acc[mt][nt];
            #pragma unroll
            for (int half = 0; half < 2; half++) {
                int m = m0 + half * 8;
                float v0 = cc[half * 2 + 0];
                float v1 = cc[half * 2 + 1];
                if constexpr (EPI == 1) {
                    if (n0 < DMODEL) {
                        *reinterpret_cast<float2*>(&O0[(size_t)m * DMODEL + n0]) = make_float2(v0, v1);
                        *reinterpret_cast<float2*>(&O2[(size_t)m * DMODEL + n0]) =
                            make_float2(f2tf_f(v0), f2tf_f(v1));
                    } else {
                        *reinterpret_cast<float2*>(&O1[(size_t)m * DMODEL + n0 - DMODEL]) = make_float2(v0, v1);
                    }
                } else if constexpr (EPI == 2) {
                    if (n0 < DMODEL) {
                        v0 = softplus_f(v0 + aux[n0]);
                        v1 = softplus_f(v1 + aux[n0 + 1]);
                        *reinterpret_cast<float2*>(&O0[(size_t)m * DMODEL + n0]) = make_float2(v0, v1);
                    } else if (n0 < 1040) {
                        *reinterpret_cast<float2*>(&O1[(size_t)m * NSTATE + (n0 - 1024)]) = make_float2(v0, v1);
                    } else if (n0 < 1056) {
                        *reinterpret_cast<float2*>(&O2[(size_t)m * NSTATE + (n0 - 1040)]) = make_float2(v0, v1);
                    }
                } else { // EPI == 3
                    float2 r = *reinterpret_cast<const float2*>(&aux[(size_t)m * DMODEL + n0]);
                    *reinterpret_cast<float2*>(&O0[(size_t)m * DMODEL + n0]) = make_float2(v0 + r.x, v1 + r.y);
                }
            }
        }
    }
}

// ---------------------------------------------------------------------------
// Sequential SSM scan + fused silu/D epilogue; 4-step-ahead prefetch blocks.
// ---------------------------------------------------------------------------
#define PF 4
__global__ __launch_bounds__(256) void scan_kernel(
    const float* __restrict__ A_log,
    const float* __restrict__ h_prev,
    const float* __restrict__ Dvec,
    float* __restrict__ h_out)
{
    int b  = blockIdx.x >> 6;
    int dg = blockIdx.x & 63;
    int n  = threadIdx.x & 15;
    int dl = threadIdx.x >> 4;
    int d  = dg * 16 + dl;

    float Acoef = -__expf(A_log[d * NSTATE + n]);
    float h  = h_prev[((size_t)b * DMODEL + d) * NSTATE + n];
    float Dd = Dvec[d];
    const bool lead = (n == 0);

    size_t idx0  = (size_t)b * LSEQ * DMODEL + d;
    size_t idxn0 = (size_t)b * LSEQ * NSTATE + n;

    float c_dt[PF], c_xin[PF], c_Bt[PF], c_Ct[PF], c_z[PF];
    #pragma unroll
    for (int j = 0; j < PF; j++) {
        c_dt[j]  = g_dt[idx0 + (size_t)j * DMODEL];
        c_xin[j] = g_xin[idx0 + (size_t)j * DMODEL];
        c_Bt[j]  = g_Bt[idxn0 + (size_t)j * NSTATE];
        c_Ct[j]  = g_Ct[idxn0 + (size_t)j * NSTATE];
        c_z[j]   = lead ? g_z[idx0 + (size_t)j * DMODEL] : 0.f;
    }

    for (int t0 = 0; t0 < LSEQ; t0 += PF) {
        float n_dt[PF], n_xin[PF], n_Bt[PF], n_Ct[PF], n_z[PF];
        if (t0 + PF < LSEQ) {
            size_t idx  = idx0  + (size_t)(t0 + PF) * DMODEL;
            size_t idxn = idxn0 + (size_t)(t0 + PF) * NSTATE;
            #pragma unroll
            for (int j = 0; j < PF; j++) {
                n_dt[j]  = g_dt[idx + (size_t)j * DMODEL];
                n_xin[j] = g_xin[idx + (size_t)j * DMODEL];
                n_Bt[j]  = g_Bt[idxn + (size_t)j * NSTATE];
                n_Ct[j]  = g_Ct[idxn + (size_t)j * NSTATE];
                n_z[j]   = lead ? g_z[idx + (size_t)j * DMODEL] : 0.f;
            }
        } else {
            #pragma unroll
            for (int j = 0; j < PF; j++) {
                n_dt[j] = 0.f; n_xin[j] = 0.f; n_Bt[j] = 0.f; n_Ct[j] = 0.f; n_z[j] = 0.f;
            }
        }

        #pragma unroll
        for (int j = 0; j < PF; j++) {
            float dA = __expf(c_dt[j] * Acoef);
            h = dA * h + (c_dt[j] * c_xin[j]) * c_Bt[j];
            float y = h * c_Ct[j];
            y += __shfl_xor_sync(0xffffffffu, y, 1);
            y += __shfl_xor_sync(0xffffffffu, y, 2);
            y += __shfl_xor_sync(0xffffffffu, y, 4);
            y += __shfl_xor_sync(0xffffffffu, y, 8);
            if (lead) {
                float zv = c_z[j];
                float sil = zv / (1.f + __expf(-zv));
                g_ssm[idx0 + (size_t)(t0 + j) * DMODEL] = f2tf_f(y * sil + c_xin[j] * Dd);
            }
        }

        #pragma unroll
        for (int j = 0; j < PF; j++) {
            c_dt[j] = n_dt[j]; c_xin[j] = n_xin[j]; c_Bt[j] = n_Bt[j];
            c_Ct[j] = n_Ct[j]; c_z[j] = n_z[j];
        }
    }
    h_out[((size_t)b * DMODEL + d) * NSTATE + n] = h;
}

// ---------------------------------------------------------------------------
// Launch
// ---------------------------------------------------------------------------
extern "C" void kernel_launch(void* const* d_in, const int* in_sizes, int n_in,
                              void* d_out, int out_size)
{
    const float* x      = (const float*)d_in[0];
    const float* h_prev = (const float*)d_in[1];
    const float* ln_g   = (const float*)d_in[2];
    const float* ln_b   = (const float*)d_in[3];
    const float* W_ig   = (const float*)d_in[4];
    const float* W_dt   = (const float*)d_in[5];
    const float* b_dt   = (const float*)d_in[6];
    const float* A_log  = (const float*)d_in[7];
    const float* W_B    = (const float*)d_in[8];
    const float* W_C    = (const float*)d_in[9];
    const float* Dv     = (const float*)d_in[10];
    const float* W_out  = (const float*)d_in[11];
    float* out = (float*)d_out;

    float *p_xnorm, *p_xin, *p_xin_r, *p_z, *p_dt, *p_Bt, *p_Ct, *p_ssm;
    float *p_wigr, *p_wbc, *p_woutr;
    cudaGetSymbolAddress((void**)&p_xnorm, g_xnorm);
    cudaGetSymbolAddress((void**)&p_xin,   g_xin);
    cudaGetSymbolAddress((void**)&p_xin_r, g_xin_r);
    cudaGetSymbolAddress((void**)&p_z,     g_z);
    cudaGetSymbolAddress((void**)&p_dt,    g_dt);
    cudaGetSymbolAddress((void**)&p_Bt,    g_Bt);
    cudaGetSymbolAddress((void**)&p_Ct,    g_Ct);
    cudaGetSymbolAddress((void**)&p_ssm,   g_ssm);
    cudaGetSymbolAddress((void**)&p_wigr,  g_wigr);
    cudaGetSymbolAddress((void**)&p_wbc,   g_wbc);
    cudaGetSymbolAddress((void**)&p_woutr, g_woutr);

    cudaFuncSetAttribute(gemm_ma<1>, cudaFuncAttributeMaxDynamicSharedMemorySize, SMEM_DYN);
    cudaFuncSetAttribute(gemm_ma<2>, cudaFuncAttributeMaxDynamicSharedMemorySize, SMEM_DYN);
    cudaFuncSetAttribute(gemm_ma<3>, cudaFuncAttributeMaxDynamicSharedMemorySize, SMEM_DYN);

    // 0. weight prep (tf32 rounding + fused W' assembly)
    prep_kernel<<<2048, 256>>>(W_ig, W_dt, W_B, W_C, W_out);

    // 1. LayerNorm (tf32-rounded output)
    layernorm_kernel<<<MTOT, 256>>>(x, ln_g, ln_b);

    // 2. x_proj = x_norm @ W_ig^T -> x_in (fp32 + tf32 copy) | z
    {
        dim3 grid(N1 / BN, MTOT / BM);
        gemm_ma<1><<<grid, 256, SMEM_DYN>>>(p_xnorm, p_wigr, p_xin, p_z, p_xin_r, nullptr);
    }

    // 3. fused: dt = softplus(x_in@W_dt^T + b_dt); Bt; Ct
    {
        dim3 grid(N2 / BN, MTOT / BM);
        gemm_ma<2><<<grid, 256, SMEM_DYN>>>(p_xin_r, p_wbc, p_dt, p_Bt, p_Ct, b_dt);
    }

    // 4. scan -> g_ssm (tf32-rounded), h_final -> out tail
    scan_kernel<<<BSZ * 64, 256>>>(A_log, h_prev, Dv, out + XTOT);

    // 5. out = x + ssm @ W_out^T
    {
        dim3 grid(N3 / BN, MTOT / BM);
        gemm_ma<3><<<grid, 256, SMEM_DYN>>>(p_ssm, p_woutr, out, nullptr, nullptr, x);
    }
}

// round 8
// speedup vs baseline: 1.9184x; 1.7586x over previous
#include <cuda_runtime.h>
#include <cuda_fp16.h>
#include <math.h>
#include <stdint.h>

// Problem constants
#define BSZ    8
#define LSEQ   1024
#define DMODEL 1024
#define NSTATE 16
#define MTOT   (BSZ * LSEQ)        // 8192
#define XTOT   (MTOT * DMODEL)     // 8388608
#define KDIM   1024

// GEMM tiling (fp16 m16n8k16)
#define BM 128
#define BN 128
#define BK 32                       // halves per chunk (2 k16 steps)
#define NSTG 4
#define NCHUNK (KDIM / BK)          // 32
#define ROWB 80                     // bytes per 64B row + 16B pad (conflict-free)
#define ASTAGE_B (128 * ROWB)       // 10240
#define STAGE_B  (2 * ASTAGE_B)     // 20480
#define SMEM_DYN (NSTG * STAGE_B)   // 81920

// N sizes
#define N1 2048
#define N2 1152                     // 1024 dt + 16 B + 16 C + 96 pad
#define N3 1024

// ---------------------------------------------------------------------------
// Scratch
// ---------------------------------------------------------------------------
__device__ __align__(256) __half g_xnormh[XTOT];        // fp16 (gemm1 A)
__device__ __align__(256) float  g_xin[XTOT];           // fp32 (scan)
__device__ __align__(256) __half g_xinh[XTOT];          // fp16 (gemm2 A)
__device__ __align__(256) float  g_z[XTOT];
__device__ __align__(256) float  g_dt[XTOT];
__device__ __align__(256) float  g_Bt[MTOT * NSTATE];
__device__ __align__(256) float  g_Ct[MTOT * NSTATE];
__device__ __align__(256) __half g_ssmh[XTOT];          // fp16 (gemm3 A)
__device__ __align__(256) __half g_wigh[N1 * KDIM];     // fp16 W_ig
__device__ __align__(256) __half g_wbch[N2 * KDIM];     // fp16 [W_dt;W_B;W_C;0]
__device__ __align__(256) __half g_wouth[N3 * KDIM];    // fp16 W_out

// ---------------------------------------------------------------------------
// Helpers
// ---------------------------------------------------------------------------
__device__ __forceinline__ uint32_t pack_h2(float a, float b) {
    __half2 h = __floats2half2_rn(a, b);
    return *reinterpret_cast<uint32_t*>(&h);
}

__device__ __forceinline__ void mma_f16(float* c, const uint32_t* a, const uint32_t* b) {
    asm volatile(
        "mma.sync.aligned.m16n8k16.row.col.f32.f16.f16.f32 "
        "{%0,%1,%2,%3}, {%4,%5,%6,%7}, {%8,%9}, {%0,%1,%2,%3};"
        : "+f"(c[0]), "+f"(c[1]), "+f"(c[2]), "+f"(c[3])
        : "r"(a[0]), "r"(a[1]), "r"(a[2]), "r"(a[3]), "r"(b[0]), "r"(b[1]));
}

__device__ __forceinline__ uint32_t smem_u32(const void* p) {
    uint32_t a;
    asm("{ .reg .u64 t; cvta.to.shared.u64 t, %1; cvt.u32.u64 %0, t; }" : "=r"(a) : "l"(p));
    return a;
}
__device__ __forceinline__ void cp16(uint32_t dst, const void* src) {
    asm volatile("cp.async.cg.shared.global [%0], [%1], 16;"
                 :: "r"(dst), "l"(__cvta_generic_to_global(src)));
}
#define CP_COMMIT() asm volatile("cp.async.commit_group;")
#define CP_WAIT2()  asm volatile("cp.async.wait_group 2;" ::: "memory")

__device__ __forceinline__ float softplus_f(float v) {
    return (v > 20.f) ? v : log1pf(expf(v));
}

// ---------------------------------------------------------------------------
// LayerNorm -> fp16 x_norm (only consumer is gemm1's A)
// ---------------------------------------------------------------------------
__global__ __launch_bounds__(256) void layernorm_kernel(
    const float* __restrict__ x,
    const float* __restrict__ g,
    const float* __restrict__ b)
{
    int row = blockIdx.x;
    int t = threadIdx.x;
    float4 v = reinterpret_cast<const float4*>(x + (size_t)row * DMODEL)[t];

    float s  = v.x + v.y + v.z + v.w;
    float sq = v.x * v.x + v.y * v.y + v.z * v.z + v.w * v.w;
    #pragma unroll
    for (int o = 16; o; o >>= 1) {
        s  += __shfl_xor_sync(0xffffffffu, s,  o);
        sq += __shfl_xor_sync(0xffffffffu, sq, o);
    }
    __shared__ float ssum[8], ssq[8], sh_mean, sh_rstd;
    int w = t >> 5;
    if ((t & 31) == 0) { ssum[w] = s; ssq[w] = sq; }
    __syncthreads();
    if (t == 0) {
        float S = 0.f, Q = 0.f;
        #pragma unroll
        for (int i = 0; i < 8; i++) { S += ssum[i]; Q += ssq[i]; }
        float mu  = S * (1.0f / DMODEL);
        float var = Q * (1.0f / DMODEL) - mu * mu;
        sh_mean = mu;
        sh_rstd = rsqrtf(var + 1e-5f);
    }
    __syncthreads();
    float mean = sh_mean, rstd = sh_rstd;

    float4 gg = reinterpret_cast<const float4*>(g)[t];
    float4 bb = reinterpret_cast<const float4*>(b)[t];
    uint2 o;
    o.x = pack_h2((v.x - mean) * rstd * gg.x + bb.x,
                  (v.y - mean) * rstd * gg.y + bb.y);
    o.y = pack_h2((v.z - mean) * rstd * gg.z + bb.z,
                  (v.w - mean) * rstd * gg.w + bb.w);
    reinterpret_cast<uint2*>(g_xnormh + (size_t)row * DMODEL)[t] = o;
}

// ---------------------------------------------------------------------------
// Weight prep: fp16-convert all B operands; assemble fused [W_dt; W_B; W_C; 0]
// (rows 1056..1151 of g_wbch stay zero from static init)
// ---------------------------------------------------------------------------
__global__ __launch_bounds__(256) void prep_kernel(
    const float* __restrict__ W_ig,
    const float* __restrict__ W_dt,
    const float* __restrict__ W_B,
    const float* __restrict__ W_C,
    const float* __restrict__ W_out)
{
    const int K4 = KDIM / 4;
    int stride = gridDim.x * blockDim.x;
    const int nig  = N1 * K4;
    const int nbc  = 1056 * K4;
    const int nout = N3 * K4;
    int total = nig + nbc + nout;
    for (int i = blockIdx.x * blockDim.x + threadIdx.x; i < total; i += stride) {
        const float4* src;
        __half* dst;
        if (i < nig) {
            src = reinterpret_cast<const float4*>(W_ig) + i;
            dst = g_wigh + (size_t)i * 4;
        } else if (i < nig + nbc) {
            int j = i - nig;
            int row = j / K4;
            int c4  = j % K4;
            const float* s;
            if (row < 1024)      s = W_dt + (size_t)row * KDIM;
            else if (row < 1040) s = W_B + (size_t)(row - 1024) * KDIM;
            else                 s = W_C + (size_t)(row - 1040) * KDIM;
            src = reinterpret_cast<const float4*>(s) + c4;
            dst = g_wbch + (size_t)j * 4;
        } else {
            int j = i - nig - nbc;
            src = reinterpret_cast<const float4*>(W_out) + j;
            dst = g_wouth + (size_t)j * 4;
        }
        float4 v = *src;
        uint2 o;
        o.x = pack_h2(v.x, v.y);
        o.y = pack_h2(v.z, v.w);
        *reinterpret_cast<uint2*>(dst) = o;
    }
}

// ---------------------------------------------------------------------------
// FP16 mma.sync m16n8k16 GEMM, cp.async 4-stage pipeline (2-chunk prefetch).
// C[m,n] = sum_k A[m,k]*B[n,k]; tile 128x128, 8 warps (2m x 4n), warp 64x32.
// SMEM: k-major rows of 64B (+16B pad -> 20-word stride, conflict-free).
// EPI 1: n<1024 -> O0 (fp32 x_in) + O2h (fp16 copy); else O1 (z, fp32)
// EPI 2: n<1024 -> softplus(v+aux[n]) -> O0; 1024-1039 -> O1(Bt);
//        1040-1055 -> O2(Ct); else discard
// EPI 3: O0 = v + aux[m*1024+n]
// ---------------------------------------------------------------------------
template<int EPI>
__global__ __launch_bounds__(256, 2) void gemm_ma(
    const __half* __restrict__ A,
    const __half* __restrict__ Bw,
    float* __restrict__ O0,
    float* __restrict__ O1,
    float* __restrict__ O2,
    __half* __restrict__ O2h,
    const float* __restrict__ aux)
{
    extern __shared__ char dsm[];
    const uint32_t dsm_addr = smem_u32(dsm);

    const int tid  = threadIdx.x;
    const int wid  = tid >> 5;
    const int lane = tid & 31;
    const int bm   = blockIdx.y * BM;
    const int bn   = blockIdx.x * BN;
    const int wm   = wid >> 2;
    const int wn   = wid & 3;
    const int g    = lane >> 2;
    const int t4   = lane & 3;

    const __half* Ag = A  + (size_t)bm * KDIM;
    const __half* Bg = Bw + (size_t)bn * KDIM;

    const int lrow = tid >> 2;      // 0..63 (+it*64)
    const int lc16 = tid & 3;       // 16B column 0..3

    auto load_chunk = [&](int c, int stg) {
        uint32_t base = dsm_addr + (uint32_t)(stg * STAGE_B);
        #pragma unroll
        for (int it = 0; it < 2; it++) {
            int row = lrow + it * 64;
            cp16(base + (uint32_t)(row * ROWB + lc16 * 16),
                 Ag + (size_t)row * KDIM + c * BK + lc16 * 8);
        }
        uint32_t baseB = base + ASTAGE_B;
        #pragma unroll
        for (int it = 0; it < 2; it++) {
            int row = lrow + it * 64;
            cp16(baseB + (uint32_t)(row * ROWB + lc16 * 16),
                 Bg + (size_t)row * KDIM + c * BK + lc16 * 8);
        }
    };

    float acc[4][4][4];
    #pragma unroll
    for (int i = 0; i < 4; i++)
        #pragma unroll
        for (int j = 0; j < 4; j++)
            #pragma unroll
            for (int r = 0; r < 4; r++) acc[i][j][r] = 0.f;

    // prologue: chunks 0,1,2
    load_chunk(0, 0); CP_COMMIT();
    load_chunk(1, 1); CP_COMMIT();
    load_chunk(2, 2); CP_COMMIT();

    for (int c = 0; c < NCHUNK; c++) {
        CP_WAIT2();           // chunk c's loads complete (2 younger in flight)
        __syncthreads();      // every warp done computing chunk c-1 ->
                              // stage (c+3)%4 == (c-1)%4 reusable

        if (c + 3 < NCHUNK) { load_chunk(c + 3, (c + 3) & (NSTG - 1)); CP_COMMIT(); }

        const char* sA = dsm + (c & (NSTG - 1)) * STAGE_B;
        const char* sAm = sA + (wm * 64) * ROWB + 4 * t4;
        const char* sBn = sA + ASTAGE_B + (wn * 32) * ROWB + 4 * t4;

        #pragma unroll
        for (int s = 0; s < 2; s++) {
            const int ko = s * 32;   // byte offset of this k16 step
            uint32_t bf[4][2];
            #pragma unroll
            for (int nt = 0; nt < 4; nt++) {
                const char* p = sBn + (nt * 8 + g) * ROWB + ko;
                bf[nt][0] = *reinterpret_cast<const uint32_t*>(p);
                bf[nt][1] = *reinterpret_cast<const uint32_t*>(p + 16);
            }
            #pragma unroll
            for (int mt = 0; mt < 4; mt++) {
                uint32_t af[4];
                const char* p0 = sAm + (mt * 16 + g) * ROWB + ko;
                const char* p1 = p0 + 8 * ROWB;
                af[0] = *reinterpret_cast<const uint32_t*>(p0);
                af[1] = *reinterpret_cast<const uint32_t*>(p1);
                af[2] = *reinterpret_cast<const uint32_t*>(p0 + 16);
                af[3] = *reinterpret_cast<const uint32_t*>(p1 + 16);
                #pragma unroll
                for (int nt = 0; nt < 4; nt++)
                    mma_f16(acc[mt][nt], af, bf[nt]);
            }
        }
    }

    // Epilogue
    #pragma unroll
    for (int mt = 0; mt < 4; mt++) {
        #pragma unroll
        for (int nt = 0; nt < 4; nt++) {
            int m0 = bm + wm * 64 + mt * 16 + g;
            int n0 = bn + wn * 32 + nt * 8 + 2 * t4;
            float* cc = acc[mt][nt];
            #pragma unroll
            for (int half_i = 0; half_i < 2; half_i++) {
                int m = m0 + half_i * 8;
                float v0 = cc[half_i * 2 + 0];
                float v1 = cc[half_i * 2 + 1];
                if constexpr (EPI == 1) {
                    if (n0 < DMODEL) {
                        *reinterpret_cast<float2*>(&O0[(size_t)m * DMODEL + n0]) = make_float2(v0, v1);
                        *reinterpret_cast<uint32_t*>(&O2h[(size_t)m * DMODEL + n0]) = pack_h2(v0, v1);
                    } else {
                        *reinterpret_cast<float2*>(&O1[(size_t)m * DMODEL + n0 - DMODEL]) = make_float2(v0, v1);
                    }
                } else if constexpr (EPI == 2) {
                    if (n0 < DMODEL) {
                        v0 = softplus_f(v0 + aux[n0]);
                        v1 = softplus_f(v1 + aux[n0 + 1]);
                        *reinterpret_cast<float2*>(&O0[(size_t)m * DMODEL + n0]) = make_float2(v0, v1);
                    } else if (n0 < 1040) {
                        *reinterpret_cast<float2*>(&O1[(size_t)m * NSTATE + (n0 - 1024)]) = make_float2(v0, v1);
                    } else if (n0 < 1056) {
                        *reinterpret_cast<float2*>(&O2[(size_t)m * NSTATE + (n0 - 1040)]) = make_float2(v0, v1);
                    }
                } else { // EPI == 3
                    float2 r = *reinterpret_cast<const float2*>(&aux[(size_t)m * DMODEL + n0]);
                    *reinterpret_cast<float2*>(&O0[(size_t)m * DMODEL + n0]) = make_float2(v0 + r.x, v1 + r.y);
                }
            }
        }
    }
}

// ---------------------------------------------------------------------------
// Sequential SSM scan + fused silu/D epilogue, 1-step-ahead prefetch.
// ssm written fp16 (only consumer is gemm3's A operand).
// ---------------------------------------------------------------------------
__global__ __launch_bounds__(256) void scan_kernel(
    const float* __restrict__ A_log,
    const float* __restrict__ h_prev,
    const float* __restrict__ Dvec,
    float* __restrict__ h_out)
{
    int b  = blockIdx.x >> 6;
    int dg = blockIdx.x & 63;
    int n  = threadIdx.x & 15;
    int dl = threadIdx.x >> 4;
    int d  = dg * 16 + dl;

    float Acoef = -__expf(A_log[d * NSTATE + n]);
    float h  = h_prev[((size_t)b * DMODEL + d) * NSTATE + n];
    float Dd = Dvec[d];
    const bool lead = (n == 0);

    size_t idx  = (size_t)b * LSEQ * DMODEL + d;
    size_t idxn = (size_t)b * LSEQ * NSTATE + n;

    float dtv = g_dt[idx];
    float xin = g_xin[idx];
    float Btv = g_Bt[idxn];
    float Ctv = g_Ct[idxn];
    float zv  = lead ? g_z[idx] : 0.f;

    for (int t = 0; t < LSEQ; t++) {
        float n_dt = 0.f, n_xin = 0.f, n_Bt = 0.f, n_Ct = 0.f, n_z = 0.f;
        if (t + 1 < LSEQ) {
            n_dt  = g_dt[idx + DMODEL];
            n_xin = g_xin[idx + DMODEL];
            n_Bt  = g_Bt[idxn + NSTATE];
            n_Ct  = g_Ct[idxn + NSTATE];
            if (lead) n_z = g_z[idx + DMODEL];
        }

        float dA = __expf(dtv * Acoef);
        h = dA * h + (dtv * xin) * Btv;
        float y = h * Ctv;
        y += __shfl_xor_sync(0xffffffffu, y, 1);
        y += __shfl_xor_sync(0xffffffffu, y, 2);
        y += __shfl_xor_sync(0xffffffffu, y, 4);
        y += __shfl_xor_sync(0xffffffffu, y, 8);

        if (lead) {
            float sil = zv / (1.f + __expf(-zv));
            g_ssmh[idx] = __float2half_rn(y * sil + xin * Dd);
        }

        dtv = n_dt; xin = n_xin; Btv = n_Bt; Ctv = n_Ct; zv = n_z;
        idx += DMODEL; idxn += NSTATE;
    }
    h_out[((size_t)b * DMODEL + d) * NSTATE + n] = h;
}

// ---------------------------------------------------------------------------
// Launch
// ---------------------------------------------------------------------------
extern "C" void kernel_launch(void* const* d_in, const int* in_sizes, int n_in,
                              void* d_out, int out_size)
{
    const float* x      = (const float*)d_in[0];
    const float* h_prev = (const float*)d_in[1];
    const float* ln_g   = (const float*)d_in[2];
    const float* ln_b   = (const float*)d_in[3];
    const float* W_ig   = (const float*)d_in[4];
    const float* W_dt   = (const float*)d_in[5];
    const float* b_dt   = (const float*)d_in[6];
    const float* A_log  = (const float*)d_in[7];
    const float* W_B    = (const float*)d_in[8];
    const float* W_C    = (const float*)d_in[9];
    const float* Dv     = (const float*)d_in[10];
    const float* W_out  = (const float*)d_in[11];
    float* out = (float*)d_out;

    float *p_xin, *p_z, *p_dt, *p_Bt, *p_Ct;
    __half *p_xnormh, *p_xinh, *p_ssmh, *p_wigh, *p_wbch, *p_wouth;
    cudaGetSymbolAddress((void**)&p_xnormh, g_xnormh);
    cudaGetSymbolAddress((void**)&p_xin,    g_xin);
    cudaGetSymbolAddress((void**)&p_xinh,   g_xinh);
    cudaGetSymbolAddress((void**)&p_z,      g_z);
    cudaGetSymbolAddress((void**)&p_dt,     g_dt);
    cudaGetSymbolAddress((void**)&p_Bt,     g_Bt);
    cudaGetSymbolAddress((void**)&p_Ct,     g_Ct);
    cudaGetSymbolAddress((void**)&p_ssmh,   g_ssmh);
    cudaGetSymbolAddress((void**)&p_wigh,   g_wigh);
    cudaGetSymbolAddress((void**)&p_wbch,   g_wbch);
    cudaGetSymbolAddress((void**)&p_wouth,  g_wouth);

    cudaFuncSetAttribute(gemm_ma<1>, cudaFuncAttributeMaxDynamicSharedMemorySize, SMEM_DYN);
    cudaFuncSetAttribute(gemm_ma<2>, cudaFuncAttributeMaxDynamicSharedMemorySize, SMEM_DYN);
    cudaFuncSetAttribute(gemm_ma<3>, cudaFuncAttributeMaxDynamicSharedMemorySize, SMEM_DYN);

    // 0. weight prep (fp16 conversion + fused W' assembly)
    prep_kernel<<<2048, 256>>>(W_ig, W_dt, W_B, W_C, W_out);

    // 1. LayerNorm (fp16 output)
    layernorm_kernel<<<MTOT, 256>>>(x, ln_g, ln_b);

    // 2. x_proj = x_norm @ W_ig^T -> x_in (fp32 + fp16 copy) | z
    {
        dim3 grid(N1 / BN, MTOT / BM);
        gemm_ma<1><<<grid, 256, SMEM_DYN>>>(p_xnormh, p_wigh, p_xin, p_z, nullptr, p_xinh, nullptr);
    }

    // 3. fused: dt = softplus(x_in@W_dt^T + b_dt); Bt; Ct
    {
        dim3 grid(N2 / BN, MTOT / BM);
        gemm_ma<2><<<grid, 256, SMEM_DYN>>>(p_xinh, p_wbch, p_dt, p_Bt, p_Ct, nullptr, b_dt);
    }

    // 4. scan -> g_ssmh (fp16), h_final -> out tail
    scan_kernel<<<BSZ * 64, 256>>>(A_log, h_prev, Dv, out + XTOT);

    // 5. out = x + ssm @ W_out^T
    {
        dim3 grid(N3 / BN, MTOT / BM);
        gemm_ma<3><<<grid, 256, SMEM_DYN>>>(p_ssmh, p_wouth, out, nullptr, nullptr, nullptr, x);
    }
}

// round 9
// speedup vs baseline: 1.9191x; 1.0004x over previous
#include <cuda_runtime.h>
#include <cuda_fp16.h>
#include <math.h>
#include <stdint.h>

// Problem constants
#define BSZ    8
#define LSEQ   1024
#define DMODEL 1024
#define NSTATE 16
#define MTOT   (BSZ * LSEQ)        // 8192
#define XTOT   (MTOT * DMODEL)     // 8388608
#define KDIM   1024

// GEMM tiling (fp16 m16n8k16)
#define BM 128
#define BN 128
#define BK 32                       // halves per chunk (2 k16 steps)
#define NSTG 4
#define NCHUNK (KDIM / BK)          // 32
#define ROWB 80                     // bytes per 64B row + 16B pad (conflict-free)
#define ASTAGE_B (128 * ROWB)       // 10240
#define STAGE_B  (2 * ASTAGE_B)     // 20480
#define SMEM_DYN (NSTG * STAGE_B)   // 81920

// N sizes
#define N1 2048
#define N2 1152                     // 1024 dt + 16 B + 16 C + 96 pad
#define N3 1024

// ---------------------------------------------------------------------------
// Scratch
// ---------------------------------------------------------------------------
__device__ __align__(256) __half g_xnormh[XTOT];        // fp16 (gemm1 A)
__device__ __align__(256) float  g_xin[XTOT];           // fp32 (scan)
__device__ __align__(256) __half g_xinh[XTOT];          // fp16 (gemm2 A)
__device__ __align__(256) float  g_z[XTOT];
__device__ __align__(256) float  g_dt[XTOT];
__device__ __align__(256) float  g_Bt[MTOT * NSTATE];
__device__ __align__(256) float  g_Ct[MTOT * NSTATE];
__device__ __align__(256) __half g_ssmh[XTOT];          // fp16 (gemm3 A)
__device__ __align__(256) __half g_wigh[N1 * KDIM];     // fp16 W_ig
__device__ __align__(256) __half g_wbch[N2 * KDIM];     // fp16 [W_dt;W_B;W_C;0]
__device__ __align__(256) __half g_wouth[N3 * KDIM];    // fp16 W_out

// ---------------------------------------------------------------------------
// Helpers
// ---------------------------------------------------------------------------
__device__ __forceinline__ uint32_t pack_h2(float a, float b) {
    __half2 h = __floats2half2_rn(a, b);
    return *reinterpret_cast<uint32_t*>(&h);
}

__device__ __forceinline__ void mma_f16(float* c, const uint32_t* a, const uint32_t* b) {
    asm volatile(
        "mma.sync.aligned.m16n8k16.row.col.f32.f16.f16.f32 "
        "{%0,%1,%2,%3}, {%4,%5,%6,%7}, {%8,%9}, {%0,%1,%2,%3};"
        : "+f"(c[0]), "+f"(c[1]), "+f"(c[2]), "+f"(c[3])
        : "r"(a[0]), "r"(a[1]), "r"(a[2]), "r"(a[3]), "r"(b[0]), "r"(b[1]));
}

__device__ __forceinline__ uint32_t smem_u32(const void* p) {
    uint32_t a;
    asm("{ .reg .u64 t; cvta.to.shared.u64 t, %1; cvt.u32.u64 %0, t; }" : "=r"(a) : "l"(p));
    return a;
}
__device__ __forceinline__ void cp16(uint32_t dst, const void* src) {
    asm volatile("cp.async.cg.shared.global [%0], [%1], 16;"
                 :: "r"(dst), "l"(__cvta_generic_to_global(src)));
}
#define CP_COMMIT() asm volatile("cp.async.commit_group;")
#define CP_WAIT2()  asm volatile("cp.async.wait_group 2;" ::: "memory")

__device__ __forceinline__ float softplus_f(float v) {
    return (v > 20.f) ? v : log1pf(expf(v));
}

// ---------------------------------------------------------------------------
// LayerNorm -> fp16 x_norm (only consumer is gemm1's A)
// ---------------------------------------------------------------------------
__global__ __launch_bounds__(256) void layernorm_kernel(
    const float* __restrict__ x,
    const float* __restrict__ g,
    const float* __restrict__ b)
{
    int row = blockIdx.x;
    int t = threadIdx.x;
    float4 v = reinterpret_cast<const float4*>(x + (size_t)row * DMODEL)[t];

    float s  = v.x + v.y + v.z + v.w;
    float sq = v.x * v.x + v.y * v.y + v.z * v.z + v.w * v.w;
    #pragma unroll
    for (int o = 16; o; o >>= 1) {
        s  += __shfl_xor_sync(0xffffffffu, s,  o);
        sq += __shfl_xor_sync(0xffffffffu, sq, o);
    }
    __shared__ float ssum[8], ssq[8], sh_mean, sh_rstd;
    int w = t >> 5;
    if ((t & 31) == 0) { ssum[w] = s; ssq[w] = sq; }
    __syncthreads();
    if (t == 0) {
        float S = 0.f, Q = 0.f;
        #pragma unroll
        for (int i = 0; i < 8; i++) { S += ssum[i]; Q += ssq[i]; }
        float mu  = S * (1.0f / DMODEL);
        float var = Q * (1.0f / DMODEL) - mu * mu;
        sh_mean = mu;
        sh_rstd = rsqrtf(var + 1e-5f);
    }
    __syncthreads();
    float mean = sh_mean, rstd = sh_rstd;

    float4 gg = reinterpret_cast<const float4*>(g)[t];
    float4 bb = reinterpret_cast<const float4*>(b)[t];
    uint2 o;
    o.x = pack_h2((v.x - mean) * rstd * gg.x + bb.x,
                  (v.y - mean) * rstd * gg.y + bb.y);
    o.y = pack_h2((v.z - mean) * rstd * gg.z + bb.z,
                  (v.w - mean) * rstd * gg.w + bb.w);
    reinterpret_cast<uint2*>(g_xnormh + (size_t)row * DMODEL)[t] = o;
}

// ---------------------------------------------------------------------------
// Weight prep: fp16-convert all B operands; assemble fused [W_dt; W_B; W_C; 0]
// (rows 1056..1151 of g_wbch stay zero from static init)
// ---------------------------------------------------------------------------
__global__ __launch_bounds__(256) void prep_kernel(
    const float* __restrict__ W_ig,
    const float* __restrict__ W_dt,
    const float* __restrict__ W_B,
    const float* __restrict__ W_C,
    const float* __restrict__ W_out)
{
    const int K4 = KDIM / 4;
    int stride = gridDim.x * blockDim.x;
    const int nig  = N1 * K4;
    const int nbc  = 1056 * K4;
    const int nout = N3 * K4;
    int total = nig + nbc + nout;
    for (int i = blockIdx.x * blockDim.x + threadIdx.x; i < total; i += stride) {
        const float4* src;
        __half* dst;
        if (i < nig) {
            src = reinterpret_cast<const float4*>(W_ig) + i;
            dst = g_wigh + (size_t)i * 4;
        } else if (i < nig + nbc) {
            int j = i - nig;
            int row = j / K4;
            int c4  = j % K4;
            const float* s;
            if (row < 1024)      s = W_dt + (size_t)row * KDIM;
            else if (row < 1040) s = W_B + (size_t)(row - 1024) * KDIM;
            else                 s = W_C + (size_t)(row - 1040) * KDIM;
            src = reinterpret_cast<const float4*>(s) + c4;
            dst = g_wbch + (size_t)j * 4;
        } else {
            int j = i - nig - nbc;
            src = reinterpret_cast<const float4*>(W_out) + j;
            dst = g_wouth + (size_t)j * 4;
        }
        float4 v = *src;
        uint2 o;
        o.x = pack_h2(v.x, v.y);
        o.y = pack_h2(v.z, v.w);
        *reinterpret_cast<uint2*>(dst) = o;
    }
}

// ---------------------------------------------------------------------------
// FP16 mma.sync m16n8k16 GEMM, cp.async 4-stage pipeline (2-chunk prefetch).
// C[m,n] = sum_k A[m,k]*B[n,k]; tile 128x128, 8 warps (2m x 4n), warp 64x32.
// SMEM: k-major rows of 64B (+16B pad -> 20-word stride, conflict-free).
// EPI 1: n<1024 -> O0 (fp32 x_in) + O2h (fp16 copy); else O1 (z, fp32)
// EPI 2: n<1024 -> softplus(v+aux[n]) -> O0; 1024-1039 -> O1(Bt);
//        1040-1055 -> O2(Ct); else discard
// EPI 3: O0 = v + aux[m*1024+n]
// ---------------------------------------------------------------------------
template<int EPI>
__global__ __launch_bounds__(256, 2) void gemm_ma(
    const __half* __restrict__ A,
    const __half* __restrict__ Bw,
    float* __restrict__ O0,
    float* __restrict__ O1,
    float* __restrict__ O2,
    __half* __restrict__ O2h,
    const float* __restrict__ aux)
{
    extern __shared__ char dsm[];
    const uint32_t dsm_addr = smem_u32(dsm);

    const int tid  = threadIdx.x;
    const int wid  = tid >> 5;
    const int lane = tid & 31;
    const int bm   = blockIdx.y * BM;
    const int bn   = blockIdx.x * BN;
    const int wm   = wid >> 2;
    const int wn   = wid & 3;
    const int g    = lane >> 2;
    const int t4   = lane & 3;

    const __half* Ag = A  + (size_t)bm * KDIM;
    const __half* Bg = Bw + (size_t)bn * KDIM;

    const int lrow = tid >> 2;      // 0..63 (+it*64)
    const int lc16 = tid & 3;       // 16B column 0..3

    auto load_chunk = [&](int c, int stg) {
        uint32_t base = dsm_addr + (uint32_t)(stg * STAGE_B);
        #pragma unroll
        for (int it = 0; it < 2; it++) {
            int row = lrow + it * 64;
            cp16(base + (uint32_t)(row * ROWB + lc16 * 16),
                 Ag + (size_t)row * KDIM + c * BK + lc16 * 8);
        }
        uint32_t baseB = base + ASTAGE_B;
        #pragma unroll
        for (int it = 0; it < 2; it++) {
            int row = lrow + it * 64;
            cp16(baseB + (uint32_t)(row * ROWB + lc16 * 16),
                 Bg + (size_t)row * KDIM + c * BK + lc16 * 8);
        }
    };

    float acc[4][4][4];
    #pragma unroll
    for (int i = 0; i < 4; i++)
        #pragma unroll
        for (int j = 0; j < 4; j++)
            #pragma unroll
            for (int r = 0; r < 4; r++) acc[i][j][r] = 0.f;

    // prologue: chunks 0,1,2
    load_chunk(0, 0); CP_COMMIT();
    load_chunk(1, 1); CP_COMMIT();
    load_chunk(2, 2); CP_COMMIT();

    for (int c = 0; c < NCHUNK; c++) {
        CP_WAIT2();           // chunk c's loads complete (2 younger in flight)
        __syncthreads();      // every warp done computing chunk c-1 ->
                              // stage (c+3)%4 == (c-1)%4 reusable

        if (c + 3 < NCHUNK) { load_chunk(c + 3, (c + 3) & (NSTG - 1)); CP_COMMIT(); }

        const char* sA = dsm + (c & (NSTG - 1)) * STAGE_B;
        const char* sAm = sA + (wm * 64) * ROWB + 4 * t4;
        const char* sBn = sA + ASTAGE_B + (wn * 32) * ROWB + 4 * t4;

        #pragma unroll
        for (int s = 0; s < 2; s++) {
            const int ko = s * 32;   // byte offset of this k16 step
            uint32_t bf[4][2];
            #pragma unroll
            for (int nt = 0; nt < 4; nt++) {
                const char* p = sBn + (nt * 8 + g) * ROWB + ko;
                bf[nt][0] = *reinterpret_cast<const uint32_t*>(p);
                bf[nt][1] = *reinterpret_cast<const uint32_t*>(p + 16);
            }
            #pragma unroll
            for (int mt = 0; mt < 4; mt++) {
                uint32_t af[4];
                const char* p0 = sAm + (mt * 16 + g) * ROWB + ko;
                const char* p1 = p0 + 8 * ROWB;
                af[0] = *reinterpret_cast<const uint32_t*>(p0);
                af[1] = *reinterpret_cast<const uint32_t*>(p1);
                af[2] = *reinterpret_cast<const uint32_t*>(p0 + 16);
                af[3] = *reinterpret_cast<const uint32_t*>(p1 + 16);
                #pragma unroll
                for (int nt = 0; nt < 4; nt++)
                    mma_f16(acc[mt][nt], af, bf[nt]);
            }
        }
    }

    // Epilogue
    #pragma unroll
    for (int mt = 0; mt < 4; mt++) {
        #pragma unroll
        for (int nt = 0; nt < 4; nt++) {
            int m0 = bm + wm * 64 + mt * 16 + g;
            int n0 = bn + wn * 32 + nt * 8 + 2 * t4;
            float* cc = acc[mt][nt];
            #pragma unroll
            for (int half_i = 0; half_i < 2; half_i++) {
                int m = m0 + half_i * 8;
                float v0 = cc[half_i * 2 + 0];
                float v1 = cc[half_i * 2 + 1];
                if constexpr (EPI == 1) {
                    if (n0 < DMODEL) {
                        *reinterpret_cast<float2*>(&O0[(size_t)m * DMODEL + n0]) = make_float2(v0, v1);
                        *reinterpret_cast<uint32_t*>(&O2h[(size_t)m * DMODEL + n0]) = pack_h2(v0, v1);
                    } else {
                        *reinterpret_cast<float2*>(&O1[(size_t)m * DMODEL + n0 - DMODEL]) = make_float2(v0, v1);
                    }
                } else if constexpr (EPI == 2) {
                    if (n0 < DMODEL) {
                        v0 = softplus_f(v0 + aux[n0]);
                        v1 = softplus_f(v1 + aux[n0 + 1]);
                        *reinterpret_cast<float2*>(&O0[(size_t)m * DMODEL + n0]) = make_float2(v0, v1);
                    } else if (n0 < 1040) {
                        *reinterpret_cast<float2*>(&O1[(size_t)m * NSTATE + (n0 - 1024)]) = make_float2(v0, v1);
                    } else if (n0 < 1056) {
                        *reinterpret_cast<float2*>(&O2[(size_t)m * NSTATE + (n0 - 1040)]) = make_float2(v0, v1);
                    }
                } else { // EPI == 3
                    float2 r = *reinterpret_cast<const float2*>(&aux[(size_t)m * DMODEL + n0]);
                    *reinterpret_cast<float2*>(&O0[(size_t)m * DMODEL + n0]) = make_float2(v0 + r.x, v1 + r.y);
                }
            }
        }
    }
}

// ---------------------------------------------------------------------------
// Sequential SSM scan + fused silu/D epilogue, 1-step-ahead prefetch.
// ssm written fp16 (only consumer is gemm3's A operand).
// ---------------------------------------------------------------------------
__global__ __launch_bounds__(256) void scan_kernel(
    const float* __restrict__ A_log,
    const float* __restrict__ h_prev,
    const float* __restrict__ Dvec,
    float* __restrict__ h_out)
{
    int b  = blockIdx.x >> 6;
    int dg = blockIdx.x & 63;
    int n  = threadIdx.x & 15;
    int dl = threadIdx.x >> 4;
    int d  = dg * 16 + dl;

    float Acoef = -__expf(A_log[d * NSTATE + n]);
    float h  = h_prev[((size_t)b * DMODEL + d) * NSTATE + n];
    float Dd = Dvec[d];
    const bool lead = (n == 0);

    size_t idx  = (size_t)b * LSEQ * DMODEL + d;
    size_t idxn = (size_t)b * LSEQ * NSTATE + n;

    float dtv = g_dt[idx];
    float xin = g_xin[idx];
    float Btv = g_Bt[idxn];
    float Ctv = g_Ct[idxn];
    float zv  = lead ? g_z[idx] : 0.f;

    for (int t = 0; t < LSEQ; t++) {
        float n_dt = 0.f, n_xin = 0.f, n_Bt = 0.f, n_Ct = 0.f, n_z = 0.f;
        if (t + 1 < LSEQ) {
            n_dt  = g_dt[idx + DMODEL];
            n_xin = g_xin[idx + DMODEL];
            n_Bt  = g_Bt[idxn + NSTATE];
            n_Ct  = g_Ct[idxn + NSTATE];
            if (lead) n_z = g_z[idx + DMODEL];
        }

        float dA = __expf(dtv * Acoef);
        h = dA * h + (dtv * xin) * Btv;
        float y = h * Ctv;
        y += __shfl_xor_sync(0xffffffffu, y, 1);
        y += __shfl_xor_sync(0xffffffffu, y, 2);
        y += __shfl_xor_sync(0xffffffffu, y, 4);
        y += __shfl_xor_sync(0xffffffffu, y, 8);

        if (lead) {
            float sil = zv / (1.f + __expf(-zv));
            g_ssmh[idx] = __float2half_rn(y * sil + xin * Dd);
        }

        dtv = n_dt; xin = n_xin; Btv = n_Bt; Ctv = n_Ct; zv = n_z;
        idx += DMODEL; idxn += NSTATE;
    }
    h_out[((size_t)b * DMODEL + d) * NSTATE + n] = h;
}

// ---------------------------------------------------------------------------
// Launch
// ---------------------------------------------------------------------------
extern "C" void kernel_launch(void* const* d_in, const int* in_sizes, int n_in,
                              void* d_out, int out_size)
{
    const float* x      = (const float*)d_in[0];
    const float* h_prev = (const float*)d_in[1];
    const float* ln_g   = (const float*)d_in[2];
    const float* ln_b   = (const float*)d_in[3];
    const float* W_ig   = (const float*)d_in[4];
    const float* W_dt   = (const float*)d_in[5];
    const float* b_dt   = (const float*)d_in[6];
    const float* A_log  = (const float*)d_in[7];
    const float* W_B    = (const float*)d_in[8];
    const float* W_C    = (const float*)d_in[9];
    const float* Dv     = (const float*)d_in[10];
    const float* W_out  = (const float*)d_in[11];
    float* out = (float*)d_out;

    float *p_xin, *p_z, *p_dt, *p_Bt, *p_Ct;
    __half *p_xnormh, *p_xinh, *p_ssmh, *p_wigh, *p_wbch, *p_wouth;
    cudaGetSymbolAddress((void**)&p_xnormh, g_xnormh);
    cudaGetSymbolAddress((void**)&p_xin,    g_xin);
    cudaGetSymbolAddress((void**)&p_xinh,   g_xinh);
    cudaGetSymbolAddress((void**)&p_z,      g_z);
    cudaGetSymbolAddress((void**)&p_dt,     g_dt);
    cudaGetSymbolAddress((void**)&p_Bt,     g_Bt);
    cudaGetSymbolAddress((void**)&p_Ct,     g_Ct);
    cudaGetSymbolAddress((void**)&p_ssmh,   g_ssmh);
    cudaGetSymbolAddress((void**)&p_wigh,   g_wigh);
    cudaGetSymbolAddress((void**)&p_wbch,   g_wbch);
    cudaGetSymbolAddress((void**)&p_wouth,  g_wouth);

    cudaFuncSetAttribute(gemm_ma<1>, cudaFuncAttributeMaxDynamicSharedMemorySize, SMEM_DYN);
    cudaFuncSetAttribute(gemm_ma<2>, cudaFuncAttributeMaxDynamicSharedMemorySize, SMEM_DYN);
    cudaFuncSetAttribute(gemm_ma<3>, cudaFuncAttributeMaxDynamicSharedMemorySize, SMEM_DYN);

    // 0. weight prep (fp16 conversion + fused W' assembly)
    prep_kernel<<<2048, 256>>>(W_ig, W_dt, W_B, W_C, W_out);

    // 1. LayerNorm (fp16 output)
    layernorm_kernel<<<MTOT, 256>>>(x, ln_g, ln_b);

    // 2. x_proj = x_norm @ W_ig^T -> x_in (fp32 + fp16 copy) | z
    {
        dim3 grid(N1 / BN, MTOT / BM);
        gemm_ma<1><<<grid, 256, SMEM_DYN>>>(p_xnormh, p_wigh, p_xin, p_z, nullptr, p_xinh, nullptr);
    }

    // 3. fused: dt = softplus(x_in@W_dt^T + b_dt); Bt; Ct
    {
        dim3 grid(N2 / BN, MTOT / BM);
        gemm_ma<2><<<grid, 256, SMEM_DYN>>>(p_xinh, p_wbch, p_dt, p_Bt, p_Ct, nullptr, b_dt);
    }

    // 4. scan -> g_ssmh (fp16), h_final -> out tail
    scan_kernel<<<BSZ * 64, 256>>>(A_log, h_prev, Dv, out + XTOT);

    // 5. out = x + ssm @ W_out^T
    {
        dim3 grid(N3 / BN, MTOT / BM);
        gemm_ma<3><<<grid, 256, SMEM_DYN>>>(p_ssmh, p_wouth, out, nullptr, nullptr, nullptr, x);
    }
}